// round 1
// baseline (speedup 1.0000x reference)
#include <cuda_runtime.h>
#include <math.h>

// Problem constants
#define Bc   4
#define Sc   2048
#define Dc   512
#define Hc   8
#define Dhc  64
#define Mrows (Bc*Sc)      // 8192
#define D3   (3*Dc)        // 1536
#define DffC (4*Dc)        // 2048

// ---- scratch (no cudaMalloc allowed; module-scope device globals) ----
__device__ float g_h  [(size_t)Mrows * Dc];
__device__ float g_qkv[(size_t)Mrows * D3];
__device__ float g_ctx[(size_t)Mrows * Dc];
__device__ float g_x1 [(size_t)Mrows * Dc];
__device__ float g_h2 [(size_t)Mrows * Dc];
__device__ float g_ff1[(size_t)Mrows * DffC];

// ============================================================
// LayerNorm: one 128-thread block per row of 512 floats
// ============================================================
__global__ void ln_kernel(const float* __restrict__ x,
                          const float* __restrict__ g,
                          const float* __restrict__ b,
                          float* __restrict__ out) {
    int row = blockIdx.x;
    int t = threadIdx.x;                 // 0..127
    const float4* xr = (const float4*)(x + (size_t)row * Dc);
    float4 v = xr[t];
    float s  = v.x + v.y + v.z + v.w;
    float s2 = v.x*v.x + v.y*v.y + v.z*v.z + v.w*v.w;
    #pragma unroll
    for (int o = 16; o > 0; o >>= 1) {
        s  += __shfl_xor_sync(0xffffffffu, s,  o);
        s2 += __shfl_xor_sync(0xffffffffu, s2, o);
    }
    __shared__ float sh[8];
    int w = t >> 5;
    if ((t & 31) == 0) { sh[w*2] = s; sh[w*2+1] = s2; }
    __syncthreads();
    s  = sh[0] + sh[2] + sh[4] + sh[6];
    s2 = sh[1] + sh[3] + sh[5] + sh[7];
    float mu  = s * (1.0f / Dc);
    float var = s2 * (1.0f / Dc) - mu * mu;
    float rstd = rsqrtf(var + 1e-5f);
    float4 gv = ((const float4*)g)[t];
    float4 bv = ((const float4*)b)[t];
    float4 o4;
    o4.x = (v.x - mu) * rstd * gv.x + bv.x;
    o4.y = (v.y - mu) * rstd * gv.y + bv.y;
    o4.z = (v.z - mu) * rstd * gv.z + bv.z;
    o4.w = (v.w - mu) * rstd * gv.w + bv.w;
    ((float4*)(out + (size_t)row * Dc))[t] = o4;
}

// ============================================================
// SGEMM: C[M,N] = A[M,K] * B[N,K]^T + bias[N]  (+epilogue)
// 128x128 block tile, BK=8, 256 threads, 8x8 per-thread microtile
// EPI: 0 = bias only, 1 = bias + residual add, 2 = bias + exact GELU
// ============================================================
template<int EPI>
__global__ __launch_bounds__(256)
void sgemm_kernel(const float* __restrict__ A,
                  const float* __restrict__ Bw,
                  const float* __restrict__ bias,
                  const float* __restrict__ res,
                  float* __restrict__ C,
                  int M, int N, int K) {
    __shared__ float As[8][128];
    __shared__ float Bs[8][128];

    int tid = threadIdx.x;
    int bm = blockIdx.y * 128;
    int bn = blockIdx.x * 128;
    int tx = tid & 15, ty = tid >> 4;

    int lrow = tid >> 1;            // 0..127
    int lcol = (tid & 1) << 2;      // 0 or 4

    const float* Ap = A  + (size_t)(bm + lrow) * K + lcol;
    const float* Bp = Bw + (size_t)(bn + lrow) * K + lcol;

    float acc[8][8];
    #pragma unroll
    for (int i = 0; i < 8; i++)
        #pragma unroll
        for (int j = 0; j < 8; j++) acc[i][j] = 0.0f;

    float4 a4 = *(const float4*)(Ap);
    float4 b4 = *(const float4*)(Bp);

    for (int k0 = 0; k0 < K; k0 += 8) {
        As[lcol+0][lrow] = a4.x; As[lcol+1][lrow] = a4.y;
        As[lcol+2][lrow] = a4.z; As[lcol+3][lrow] = a4.w;
        Bs[lcol+0][lrow] = b4.x; Bs[lcol+1][lrow] = b4.y;
        Bs[lcol+2][lrow] = b4.z; Bs[lcol+3][lrow] = b4.w;
        __syncthreads();

        if (k0 + 8 < K) {           // prefetch next tile into registers
            a4 = *(const float4*)(Ap + k0 + 8);
            b4 = *(const float4*)(Bp + k0 + 8);
        }

        #pragma unroll
        for (int k = 0; k < 8; k++) {
            float ra[8], rb[8];
            #pragma unroll
            for (int i = 0; i < 8; i++) ra[i] = As[k][ty*8 + i];
            #pragma unroll
            for (int j = 0; j < 8; j++) rb[j] = Bs[k][tx*8 + j];
            #pragma unroll
            for (int i = 0; i < 8; i++)
                #pragma unroll
                for (int j = 0; j < 8; j++)
                    acc[i][j] = fmaf(ra[i], rb[j], acc[i][j]);
        }
        __syncthreads();
    }

    #pragma unroll
    for (int i = 0; i < 8; i++) {
        int m = bm + ty*8 + i;
        #pragma unroll
        for (int j = 0; j < 8; j++) {
            int n = bn + tx*8 + j;
            float v = acc[i][j] + bias[n];
            if (EPI == 1) v += res[(size_t)m * N + n];
            if (EPI == 2) v = 0.5f * v * (1.0f + erff(v * 0.70710678118654752f));
            C[(size_t)m * N + n] = v;
        }
    }
}

// ============================================================
// Local attention: one warp per (b, s, h); window radius 4 (9 keys)
// qkv layout: row m=b*S+s, [q(0:512) | k(512:1024) | v(1024:1536)]
// ============================================================
__global__ void attn_kernel(const float* __restrict__ qkv,
                            float* __restrict__ ctx) {
    int gwarp = (blockIdx.x * blockDim.x + threadIdx.x) >> 5;
    int lane = threadIdx.x & 31;
    int h  = gwarp & (Hc - 1);
    int bs = gwarp >> 3;            // 0..8191
    int s  = bs & (Sc - 1);
    int rowbase = bs - s;           // b*S

    const float* qr = qkv + (size_t)bs * D3 + h * Dhc;
    float q0 = qr[lane], q1 = qr[lane + 32];

    float e[9];
    float mx = -INFINITY;
    #pragma unroll
    for (int jj = 0; jj < 9; jj++) {
        int j = s - 4 + jj;
        float sc = -INFINITY;
        if (j >= 0 && j < Sc) {
            const float* kr = qkv + (size_t)(rowbase + j) * D3 + Dc + h * Dhc;
            float p = q0 * kr[lane] + q1 * kr[lane + 32];
            #pragma unroll
            for (int o = 16; o > 0; o >>= 1)
                p += __shfl_xor_sync(0xffffffffu, p, o);
            sc = p * 0.125f;        // 1/sqrt(64)
        }
        e[jj] = sc;
        mx = fmaxf(mx, sc);
    }
    float sum = 0.0f;
    #pragma unroll
    for (int jj = 0; jj < 9; jj++) {
        e[jj] = expf(e[jj] - mx);   // exp(-inf) = 0 for masked positions
        sum += e[jj];
    }
    float inv = 1.0f / sum;
    float c0 = 0.0f, c1 = 0.0f;
    #pragma unroll
    for (int jj = 0; jj < 9; jj++) {
        int j = s - 4 + jj;
        if (j >= 0 && j < Sc) {
            const float* vr = qkv + (size_t)(rowbase + j) * D3 + 2*Dc + h * Dhc;
            float w = e[jj] * inv;
            c0 = fmaf(w, vr[lane],      c0);
            c1 = fmaf(w, vr[lane + 32], c1);
        }
    }
    float* o = ctx + (size_t)bs * Dc + h * Dhc;
    o[lane]      = c0;
    o[lane + 32] = c1;
}

// ============================================================
extern "C" void kernel_launch(void* const* d_in, const int* in_sizes, int n_in,
                              void* d_out, int out_size) {
    const float* x     = (const float*)d_in[0];
    const float* in_w  = (const float*)d_in[1];
    const float* in_b  = (const float*)d_in[2];
    const float* out_w = (const float*)d_in[3];
    const float* out_b = (const float*)d_in[4];
    const float* ff_w1 = (const float*)d_in[5];
    const float* ff_b1 = (const float*)d_in[6];
    const float* ff_w2 = (const float*)d_in[7];
    const float* ff_b2 = (const float*)d_in[8];
    const float* ln1_g = (const float*)d_in[9];
    const float* ln1_b = (const float*)d_in[10];
    const float* ln2_g = (const float*)d_in[11];
    const float* ln2_b = (const float*)d_in[12];
    float* out = (float*)d_out;

    float *h, *qkv, *ctx, *x1, *h2, *ff1;
    cudaGetSymbolAddress((void**)&h,   g_h);
    cudaGetSymbolAddress((void**)&qkv, g_qkv);
    cudaGetSymbolAddress((void**)&ctx, g_ctx);
    cudaGetSymbolAddress((void**)&x1,  g_x1);
    cudaGetSymbolAddress((void**)&h2,  g_h2);
    cudaGetSymbolAddress((void**)&ff1, g_ff1);

    // 1) h = LN1(x)
    ln_kernel<<<Mrows, 128>>>(x, ln1_g, ln1_b, h);
    // 2) qkv = h @ in_proj_w^T + in_proj_b        [8192 x 1536]
    sgemm_kernel<0><<<dim3(D3/128, Mrows/128), 256>>>(h, in_w, in_b, nullptr, qkv,
                                                      Mrows, D3, Dc);
    // 3) local attention -> ctx                    [8192 x 512]
    attn_kernel<<<(Mrows * Hc * 32) / 256, 256>>>(qkv, ctx);
    // 4) x1 = x + ctx @ out_w^T + out_b
    sgemm_kernel<1><<<dim3(Dc/128, Mrows/128), 256>>>(ctx, out_w, out_b, x, x1,
                                                      Mrows, Dc, Dc);
    // 5) h2 = LN2(x1)
    ln_kernel<<<Mrows, 128>>>(x1, ln2_g, ln2_b, h2);
    // 6) ff1 = gelu(h2 @ ff_w1^T + ff_b1)          [8192 x 2048]
    sgemm_kernel<2><<<dim3(DffC/128, Mrows/128), 256>>>(h2, ff_w1, ff_b1, nullptr, ff1,
                                                        Mrows, DffC, Dc);
    // 7) out = x1 + ff1 @ ff_w2^T + ff_b2
    sgemm_kernel<1><<<dim3(Dc/128, Mrows/128), 256>>>(ff1, ff_w2, ff_b2, x1, out,
                                                      Mrows, Dc, DffC);
}

// round 3
// speedup vs baseline: 2.8242x; 2.8242x over previous
#include <cuda_runtime.h>
#include <cuda_bf16.h>
#include <math.h>
#include <stdint.h>

// Problem constants
#define Bc   4
#define Sc   2048
#define Dc   512
#define Hc   8
#define Dhc  64
#define Mrows (Bc*Sc)      // 8192
#define D3   (3*Dc)        // 1536
#define DffC (4*Dc)        // 2048

// ---- scratch (device globals; no cudaMalloc allowed) ----
__device__ __nv_bfloat16 g_acthi[(size_t)Mrows * Dc];
__device__ __nv_bfloat16 g_actlo[(size_t)Mrows * Dc];
__device__ __nv_bfloat16 g_ffhi [(size_t)Mrows * DffC];
__device__ __nv_bfloat16 g_fflo [(size_t)Mrows * DffC];
__device__ __nv_bfloat16 g_whi  [3145728];
__device__ __nv_bfloat16 g_wlo  [3145728];
__device__ float         g_qkv  [(size_t)Mrows * D3];
__device__ float         g_x1   [(size_t)Mrows * Dc];

// weight offsets inside g_whi/g_wlo
#define WOFF_IN   0
#define WOFF_OUT  786432
#define WOFF_FF1  1048576
#define WOFF_FF2  2097152

// ============================================================
// helpers
// ============================================================
__device__ __forceinline__ uint32_t smem_u32(const void* p) {
    uint32_t a;
    asm("{ .reg .u64 t; cvta.to.shared.u64 t, %1; cvt.u32.u64 %0, t; }" : "=r"(a) : "l"(p));
    return a;
}
__device__ __forceinline__ uint32_t sw128(uint32_t o) { return o ^ ((o >> 3) & 0x70); }

// split fp32 pair into bf16 hi-pair and lo-pair (packed b32)
__device__ __forceinline__ void split2(float x, float y, uint32_t& hi, uint32_t& lo) {
    __nv_bfloat162 h = __floats2bfloat162_rn(x, y);
    float rx = x - __bfloat162float(h.x);
    float ry = y - __bfloat162float(h.y);
    __nv_bfloat162 l = __floats2bfloat162_rn(rx, ry);
    hi = *reinterpret_cast<uint32_t*>(&h);
    lo = *reinterpret_cast<uint32_t*>(&l);
}

__device__ __forceinline__ void cp16(uint32_t dst, const void* src) {
    asm volatile("cp.async.cg.shared.global [%0], [%1], 16;" :: "r"(dst), "l"(src) : "memory");
}
#define CP_COMMIT() asm volatile("cp.async.commit_group;" ::: "memory")
#define CP_WAIT(n)  asm volatile("cp.async.wait_group %0;" :: "n"(n) : "memory")

__device__ __forceinline__ void ldm_x4(uint32_t* r, uint32_t addr) {
    asm volatile("ldmatrix.sync.aligned.m8n8.x4.shared.b16 {%0,%1,%2,%3}, [%4];"
                 : "=r"(r[0]), "=r"(r[1]), "=r"(r[2]), "=r"(r[3]) : "r"(addr));
}
__device__ __forceinline__ void ldm_x2(uint32_t* r, uint32_t addr) {
    asm volatile("ldmatrix.sync.aligned.m8n8.x2.shared.b16 {%0,%1}, [%2];"
                 : "=r"(r[0]), "=r"(r[1]) : "r"(addr));
}
__device__ __forceinline__ void mma_bf16(float* c, const uint32_t* a, const uint32_t* b) {
    asm volatile("mma.sync.aligned.m16n8k16.row.col.f32.bf16.bf16.f32 "
                 "{%0,%1,%2,%3}, {%4,%5,%6,%7}, {%8,%9}, {%0,%1,%2,%3};"
                 : "+f"(c[0]), "+f"(c[1]), "+f"(c[2]), "+f"(c[3])
                 : "r"(a[0]), "r"(a[1]), "r"(a[2]), "r"(a[3]), "r"(b[0]), "r"(b[1]));
}

// ============================================================
// weight fp32 -> bf16 hi/lo split (once per launch, tiny)
// ============================================================
__global__ void wconv_kernel(const float* __restrict__ w,
                             __nv_bfloat16* __restrict__ hi,
                             __nv_bfloat16* __restrict__ lo, int n4) {
    int i = blockIdx.x * 256 + threadIdx.x;
    if (i >= n4) return;
    float4 v = ((const float4*)w)[i];
    uint32_t h0, l0, h1, l1;
    split2(v.x, v.y, h0, l0);
    split2(v.z, v.w, h1, l1);
    ((uint2*)hi)[i] = make_uint2(h0, h1);
    ((uint2*)lo)[i] = make_uint2(l0, l1);
}

// ============================================================
// LayerNorm fused with bf16 hi/lo split output
// ============================================================
__global__ void ln_split_kernel(const float* __restrict__ x,
                                const float* __restrict__ g,
                                const float* __restrict__ b,
                                __nv_bfloat16* __restrict__ hi,
                                __nv_bfloat16* __restrict__ lo) {
    int row = blockIdx.x;
    int t = threadIdx.x;                 // 0..127
    const float4* xr = (const float4*)(x + (size_t)row * Dc);
    float4 v = xr[t];
    float s  = v.x + v.y + v.z + v.w;
    float s2 = v.x*v.x + v.y*v.y + v.z*v.z + v.w*v.w;
    #pragma unroll
    for (int o = 16; o > 0; o >>= 1) {
        s  += __shfl_xor_sync(0xffffffffu, s,  o);
        s2 += __shfl_xor_sync(0xffffffffu, s2, o);
    }
    __shared__ float sh[8];
    int w = t >> 5;
    if ((t & 31) == 0) { sh[w*2] = s; sh[w*2+1] = s2; }
    __syncthreads();
    s  = sh[0] + sh[2] + sh[4] + sh[6];
    s2 = sh[1] + sh[3] + sh[5] + sh[7];
    float mu  = s * (1.0f / Dc);
    float var = s2 * (1.0f / Dc) - mu * mu;
    float rstd = rsqrtf(var + 1e-5f);
    float4 gv = ((const float4*)g)[t];
    float4 bv = ((const float4*)b)[t];
    float o0 = (v.x - mu) * rstd * gv.x + bv.x;
    float o1 = (v.y - mu) * rstd * gv.y + bv.y;
    float o2 = (v.z - mu) * rstd * gv.z + bv.z;
    float o3 = (v.w - mu) * rstd * gv.w + bv.w;
    uint32_t h0, l0, h1, l1;
    split2(o0, o1, h0, l0);
    split2(o2, o3, h1, l1);
    size_t base = (size_t)row * Dc + t * 4;
    *(uint2*)(hi + base) = make_uint2(h0, h1);
    *(uint2*)(lo + base) = make_uint2(l0, l1);
}

// ============================================================
// split-bf16 GEMM via mma.sync: C[M,N] = A[M,K] @ B[N,K]^T + bias
// 128x128 block, 8 warps (2m x 4n, each 64x32), BK=64, 2-stage cp.async
// EPI: 0=bias->fp32, 1=bias+residual->fp32, 2=bias+GELU->bf16 hi/lo
// ============================================================
#define TB  16384            // one 128x64 bf16 tile
#define STB 65536            // stage bytes (Ahi,Alo,Bhi,Blo)
#define SM_SZ (2*STB)        // 131072

template<int EPI>
__global__ __launch_bounds__(256, 1)
void gemm_mma(const __nv_bfloat16* __restrict__ Ahi, const __nv_bfloat16* __restrict__ Alo,
              const __nv_bfloat16* __restrict__ Bhi, const __nv_bfloat16* __restrict__ Blo,
              const float* __restrict__ bias, const float* __restrict__ res,
              float* __restrict__ C,
              __nv_bfloat16* __restrict__ Chi, __nv_bfloat16* __restrict__ Clo,
              int M, int N, int K)
{
    extern __shared__ __align__(128) char smem[];
    uint32_t sb = smem_u32(smem);
    int tid = threadIdx.x;
    int lane = tid & 31, wid = tid >> 5;
    int bm = blockIdx.y * 128, bn = blockIdx.x * 128;
    int m0 = (wid & 1) * 64;          // warp tile: 64 (m) x 32 (n)
    int n0 = (wid >> 1) * 32;

    float acc[4][4][4];
    #pragma unroll
    for (int i = 0; i < 4; i++)
        #pragma unroll
        for (int j = 0; j < 4; j++)
            #pragma unroll
            for (int k = 0; k < 4; k++) acc[i][j][k] = 0.0f;

    auto load_stage = [&](int st, int k0) {
        uint32_t base = sb + st * STB;
        #pragma unroll
        for (int t = 0; t < 4; t++) {
            int chunk = tid + t * 256;          // 0..1023
            int r  = chunk >> 3;                // row 0..127
            int cc = chunk & 7;                 // 16B column chunk
            uint32_t d = sw128((uint32_t)(r * 128 + cc * 16));
            size_t aoff = (size_t)(bm + r) * K + k0 + cc * 8;
            size_t boff = (size_t)(bn + r) * K + k0 + cc * 8;
            cp16(base + d,          Ahi + aoff);
            cp16(base + TB + d,     Alo + aoff);
            cp16(base + 2*TB + d,   Bhi + boff);
            cp16(base + 3*TB + d,   Blo + boff);
        }
    };

    int nk = K >> 6;
    load_stage(0, 0);
    CP_COMMIT();

    for (int ch = 0; ch < nk; ch++) {
        if (ch + 1 < nk) {
            load_stage((ch + 1) & 1, (ch + 1) * 64);
            CP_COMMIT();
            CP_WAIT(1);
        } else {
            CP_WAIT(0);
        }
        __syncthreads();

        uint32_t abase = sb + (ch & 1) * STB;
        uint32_t bbase = abase + 2 * TB;

        #pragma unroll
        for (int ks = 0; ks < 4; ks++) {
            int k0 = ks * 16;
            uint32_t ahi[4][4], alo[4][4], bhi[4][2], blo[4][2];
            #pragma unroll
            for (int mi = 0; mi < 4; mi++) {
                int row = m0 + mi*16 + (lane & 7) + ((lane >> 3) & 1) * 8;
                int col = k0 + (lane >> 4) * 8;
                uint32_t o = sw128((uint32_t)(row * 128 + col * 2));
                ldm_x4(ahi[mi], abase + o);
                ldm_x4(alo[mi], abase + TB + o);
            }
            #pragma unroll
            for (int ni = 0; ni < 4; ni++) {
                int row = n0 + ni*8 + (lane & 7);
                int col = k0 + ((lane >> 3) & 1) * 8;
                uint32_t o = sw128((uint32_t)(row * 128 + col * 2));
                ldm_x2(bhi[ni], bbase + o);
                ldm_x2(blo[ni], bbase + TB + o);
            }
            #pragma unroll
            for (int mi = 0; mi < 4; mi++)
                #pragma unroll
                for (int ni = 0; ni < 4; ni++) {
                    mma_bf16(acc[mi][ni], ahi[mi], bhi[ni]);
                    mma_bf16(acc[mi][ni], ahi[mi], blo[ni]);
                    mma_bf16(acc[mi][ni], alo[mi], bhi[ni]);
                }
        }
        __syncthreads();
    }

    // epilogue: direct stores (each thread owns 2 consecutive cols per frag)
    int g = lane >> 2, t = lane & 3;
    #pragma unroll
    for (int mi = 0; mi < 4; mi++) {
        #pragma unroll
        for (int ni = 0; ni < 4; ni++) {
            int col = bn + n0 + ni*8 + t*2;
            float b0 = bias[col], b1 = bias[col + 1];
            #pragma unroll
            for (int half = 0; half < 2; half++) {
                int row = bm + m0 + mi*16 + g + half*8;
                float v0 = acc[mi][ni][half*2 + 0] + b0;
                float v1 = acc[mi][ni][half*2 + 1] + b1;
                size_t off = (size_t)row * N + col;
                if (EPI == 1) {
                    float2 r2 = *(const float2*)(res + off);
                    v0 += r2.x; v1 += r2.y;
                }
                if (EPI == 2) {
                    v0 = 0.5f * v0 * (1.0f + erff(v0 * 0.7071067811865475f));
                    v1 = 0.5f * v1 * (1.0f + erff(v1 * 0.7071067811865475f));
                    uint32_t h, l;
                    split2(v0, v1, h, l);
                    *(uint32_t*)(Chi + off) = h;
                    *(uint32_t*)(Clo + off) = l;
                } else {
                    *(float2*)(C + off) = make_float2(v0, v1);
                }
            }
        }
    }
}

// ============================================================
// Local attention: one warp per (b,s,h); outputs ctx as bf16 hi/lo
// ============================================================
__global__ void attn_kernel(const float* __restrict__ qkv,
                            __nv_bfloat16* __restrict__ ctxhi,
                            __nv_bfloat16* __restrict__ ctxlo) {
    int gwarp = (blockIdx.x * blockDim.x + threadIdx.x) >> 5;
    int lane = threadIdx.x & 31;
    int h  = gwarp & (Hc - 1);
    int bs = gwarp >> 3;
    int s  = bs & (Sc - 1);
    int rowbase = bs - s;

    const float* qr = qkv + (size_t)bs * D3 + h * Dhc;
    float q0 = qr[lane], q1 = qr[lane + 32];

    float e[9];
    float mx = -INFINITY;
    #pragma unroll
    for (int jj = 0; jj < 9; jj++) {
        int j = s - 4 + jj;
        float sc = -INFINITY;
        if (j >= 0 && j < Sc) {
            const float* kr = qkv + (size_t)(rowbase + j) * D3 + Dc + h * Dhc;
            float p = q0 * kr[lane] + q1 * kr[lane + 32];
            #pragma unroll
            for (int o = 16; o > 0; o >>= 1)
                p += __shfl_xor_sync(0xffffffffu, p, o);
            sc = p * 0.125f;
        }
        e[jj] = sc;
        mx = fmaxf(mx, sc);
    }
    float sum = 0.0f;
    #pragma unroll
    for (int jj = 0; jj < 9; jj++) {
        e[jj] = expf(e[jj] - mx);
        sum += e[jj];
    }
    float inv = 1.0f / sum;
    float c0 = 0.0f, c1 = 0.0f;
    #pragma unroll
    for (int jj = 0; jj < 9; jj++) {
        int j = s - 4 + jj;
        if (j >= 0 && j < Sc) {
            const float* vr = qkv + (size_t)(rowbase + j) * D3 + 2*Dc + h * Dhc;
            float w = e[jj] * inv;
            c0 = fmaf(w, vr[lane],      c0);
            c1 = fmaf(w, vr[lane + 32], c1);
        }
    }
    size_t i0 = (size_t)bs * Dc + h * Dhc + lane;
    size_t i1 = i0 + 32;
    __nv_bfloat16 h0 = __float2bfloat16(c0);
    __nv_bfloat16 h1 = __float2bfloat16(c1);
    ctxhi[i0] = h0;
    ctxhi[i1] = h1;
    ctxlo[i0] = __float2bfloat16(c0 - __bfloat162float(h0));
    ctxlo[i1] = __float2bfloat16(c1 - __bfloat162float(h1));
}

// ============================================================
extern "C" void kernel_launch(void* const* d_in, const int* in_sizes, int n_in,
                              void* d_out, int out_size) {
    const float* x     = (const float*)d_in[0];
    const float* in_w  = (const float*)d_in[1];
    const float* in_b  = (const float*)d_in[2];
    const float* out_w = (const float*)d_in[3];
    const float* out_b = (const float*)d_in[4];
    const float* ff_w1 = (const float*)d_in[5];
    const float* ff_b1 = (const float*)d_in[6];
    const float* ff_w2 = (const float*)d_in[7];
    const float* ff_b2 = (const float*)d_in[8];
    const float* ln1_g = (const float*)d_in[9];
    const float* ln1_b = (const float*)d_in[10];
    const float* ln2_g = (const float*)d_in[11];
    const float* ln2_b = (const float*)d_in[12];
    float* out = (float*)d_out;

    __nv_bfloat16 *acthi, *actlo, *ffhi, *fflo, *whi, *wlo;
    float *qkv, *x1;
    cudaGetSymbolAddress((void**)&acthi, g_acthi);
    cudaGetSymbolAddress((void**)&actlo, g_actlo);
    cudaGetSymbolAddress((void**)&ffhi,  g_ffhi);
    cudaGetSymbolAddress((void**)&fflo,  g_fflo);
    cudaGetSymbolAddress((void**)&whi,   g_whi);
    cudaGetSymbolAddress((void**)&wlo,   g_wlo);
    cudaGetSymbolAddress((void**)&qkv,   g_qkv);
    cudaGetSymbolAddress((void**)&x1,    g_x1);

    cudaFuncSetAttribute(gemm_mma<0>, cudaFuncAttributeMaxDynamicSharedMemorySize, SM_SZ);
    cudaFuncSetAttribute(gemm_mma<1>, cudaFuncAttributeMaxDynamicSharedMemorySize, SM_SZ);
    cudaFuncSetAttribute(gemm_mma<2>, cudaFuncAttributeMaxDynamicSharedMemorySize, SM_SZ);

    // weight splits (fp32 -> bf16 hi/lo), small
    wconv_kernel<<<768,  256>>>(in_w,  whi + WOFF_IN,  wlo + WOFF_IN,  196608);
    wconv_kernel<<<256,  256>>>(out_w, whi + WOFF_OUT, wlo + WOFF_OUT, 65536);
    wconv_kernel<<<1024, 256>>>(ff_w1, whi + WOFF_FF1, wlo + WOFF_FF1, 262144);
    wconv_kernel<<<1024, 256>>>(ff_w2, whi + WOFF_FF2, wlo + WOFF_FF2, 262144);

    // 1) act = split(LN1(x))
    ln_split_kernel<<<Mrows, 128>>>(x, ln1_g, ln1_b, acthi, actlo);
    // 2) qkv = act @ in_w^T + in_b   (fp32 out)
    gemm_mma<0><<<dim3(D3/128, Mrows/128), 256, SM_SZ>>>(
        acthi, actlo, whi + WOFF_IN, wlo + WOFF_IN, in_b, nullptr,
        qkv, nullptr, nullptr, Mrows, D3, Dc);
    // 3) ctx = attention(qkv) -> act hi/lo
    attn_kernel<<<(Mrows * Hc * 32) / 256, 256>>>(qkv, acthi, actlo);
    // 4) x1 = x + ctx @ out_w^T + out_b
    gemm_mma<1><<<dim3(Dc/128, Mrows/128), 256, SM_SZ>>>(
        acthi, actlo, whi + WOFF_OUT, wlo + WOFF_OUT, out_b, x,
        x1, nullptr, nullptr, Mrows, Dc, Dc);
    // 5) act = split(LN2(x1))
    ln_split_kernel<<<Mrows, 128>>>(x1, ln2_g, ln2_b, acthi, actlo);
    // 6) ff = split(gelu(act @ ff_w1^T + ff_b1))
    gemm_mma<2><<<dim3(DffC/128, Mrows/128), 256, SM_SZ>>>(
        acthi, actlo, whi + WOFF_FF1, wlo + WOFF_FF1, ff_b1, nullptr,
        nullptr, ffhi, fflo, Mrows, DffC, Dc);
    // 7) out = x1 + ff @ ff_w2^T + ff_b2
    gemm_mma<1><<<dim3(Dc/128, Mrows/128), 256, SM_SZ>>>(
        ffhi, fflo, whi + WOFF_FF2, wlo + WOFF_FF2, ff_b2, x1,
        out, nullptr, nullptr, Mrows, Dc, DffC);
}

// round 4
// speedup vs baseline: 3.3453x; 1.1845x over previous
#include <cuda_runtime.h>
#include <cuda_bf16.h>
#include <cuda_fp16.h>
#include <math.h>
#include <stdint.h>

// Problem constants
#define Bc   4
#define Sc   2048
#define Dc   512
#define Hc   8
#define Dhc  64
#define Mrows (Bc*Sc)      // 8192
#define D3   (3*Dc)        // 1536
#define DffC (4*Dc)        // 2048

// ---- scratch (device globals; no cudaMalloc allowed) ----
__device__ __nv_bfloat16 g_whi  [1048576];   // in_w(786432) + out_w(262144), bf16 hi
__device__ __nv_bfloat16 g_wlo  [1048576];
__device__ __half        g_fwhi [2097152];   // ff_w1(1048576) + ff_w2(1048576), fp16(32*w) hi
__device__ __half        g_fwlo [2097152];
__device__ __nv_bfloat16 g_acthi[(size_t)Mrows * Dc];
__device__ __nv_bfloat16 g_actlo[(size_t)Mrows * Dc];
__device__ __half        g_a16  [(size_t)Mrows * Dc];    // LN2 out / 32
__device__ __half        g_ff16 [(size_t)Mrows * DffC];  // gelu out / 32
__device__ float         g_qkv  [(size_t)Mrows * D3];
__device__ float         g_x1   [(size_t)Mrows * Dc];

#define WOFF_OUT  786432
#define FWOFF_FF2 1048576

// ============================================================
// helpers
// ============================================================
__device__ __forceinline__ uint32_t smem_u32(const void* p) {
    uint32_t a;
    asm("{ .reg .u64 t; cvta.to.shared.u64 t, %1; cvt.u32.u64 %0, t; }" : "=r"(a) : "l"(p));
    return a;
}
__device__ __forceinline__ uint32_t sw128(uint32_t o) { return o ^ ((o >> 3) & 0x70); }

__device__ __forceinline__ void split2_bf(float x, float y, uint32_t& hi, uint32_t& lo) {
    __nv_bfloat162 h = __floats2bfloat162_rn(x, y);
    float rx = x - __bfloat162float(h.x);
    float ry = y - __bfloat162float(h.y);
    __nv_bfloat162 l = __floats2bfloat162_rn(rx, ry);
    hi = *reinterpret_cast<uint32_t*>(&h);
    lo = *reinterpret_cast<uint32_t*>(&l);
}
__device__ __forceinline__ void split2_f16(float x, float y, uint32_t& hi, uint32_t& lo) {
    __half2 h = __floats2half2_rn(x, y);
    float rx = x - __half2float(h.x);
    float ry = y - __half2float(h.y);
    __half2 l = __floats2half2_rn(rx, ry);
    hi = *reinterpret_cast<uint32_t*>(&h);
    lo = *reinterpret_cast<uint32_t*>(&l);
}

__device__ __forceinline__ void cp16(uint32_t dst, const void* src) {
    asm volatile("cp.async.cg.shared.global [%0], [%1], 16;" :: "r"(dst), "l"(src) : "memory");
}
#define CP_COMMIT() asm volatile("cp.async.commit_group;" ::: "memory")
#define CP_WAIT(n)  asm volatile("cp.async.wait_group %0;" :: "n"(n) : "memory")

__device__ __forceinline__ void ldm_x4(uint32_t* r, uint32_t addr) {
    asm volatile("ldmatrix.sync.aligned.m8n8.x4.shared.b16 {%0,%1,%2,%3}, [%4];"
                 : "=r"(r[0]), "=r"(r[1]), "=r"(r[2]), "=r"(r[3]) : "r"(addr));
}
__device__ __forceinline__ void ldm_x2(uint32_t* r, uint32_t addr) {
    asm volatile("ldmatrix.sync.aligned.m8n8.x2.shared.b16 {%0,%1}, [%2];"
                 : "=r"(r[0]), "=r"(r[1]) : "r"(addr));
}
__device__ __forceinline__ void mma_bf16(float* c, const uint32_t* a, const uint32_t* b) {
    asm volatile("mma.sync.aligned.m16n8k16.row.col.f32.bf16.bf16.f32 "
                 "{%0,%1,%2,%3}, {%4,%5,%6,%7}, {%8,%9}, {%0,%1,%2,%3};"
                 : "+f"(c[0]), "+f"(c[1]), "+f"(c[2]), "+f"(c[3])
                 : "r"(a[0]), "r"(a[1]), "r"(a[2]), "r"(a[3]), "r"(b[0]), "r"(b[1]));
}
__device__ __forceinline__ void mma_f16(float* c, const uint32_t* a, const uint32_t* b) {
    asm volatile("mma.sync.aligned.m16n8k16.row.col.f32.f16.f16.f32 "
                 "{%0,%1,%2,%3}, {%4,%5,%6,%7}, {%8,%9}, {%0,%1,%2,%3};"
                 : "+f"(c[0]), "+f"(c[1]), "+f"(c[2]), "+f"(c[3])
                 : "r"(a[0]), "r"(a[1]), "r"(a[2]), "r"(a[3]), "r"(b[0]), "r"(b[1]));
}

// ============================================================
// weight conversions (once per launch, tiny)
// ============================================================
__global__ void wconv_bf16(const float* __restrict__ w,
                           __nv_bfloat16* __restrict__ hi,
                           __nv_bfloat16* __restrict__ lo, int n4) {
    int i = blockIdx.x * 256 + threadIdx.x;
    if (i >= n4) return;
    float4 v = ((const float4*)w)[i];
    uint32_t h0, l0, h1, l1;
    split2_bf(v.x, v.y, h0, l0);
    split2_bf(v.z, v.w, h1, l1);
    ((uint2*)hi)[i] = make_uint2(h0, h1);
    ((uint2*)lo)[i] = make_uint2(l0, l1);
}
__global__ void wconv_f16s(const float* __restrict__ w,
                           __half* __restrict__ hi,
                           __half* __restrict__ lo, int n4) {
    int i = blockIdx.x * 256 + threadIdx.x;
    if (i >= n4) return;
    float4 v = ((const float4*)w)[i];
    uint32_t h0, l0, h1, l1;
    split2_f16(v.x * 32.0f, v.y * 32.0f, h0, l0);
    split2_f16(v.z * 32.0f, v.w * 32.0f, h1, l1);
    ((uint2*)hi)[i] = make_uint2(h0, h1);
    ((uint2*)lo)[i] = make_uint2(l0, l1);
}

// ============================================================
// LayerNorm variants
// ============================================================
template<int MODE>  // 0: bf16 hi+lo out; 1: fp16 hi (/32) out
__global__ void ln_kernel(const float* __restrict__ x,
                          const float* __restrict__ g,
                          const float* __restrict__ b,
                          __nv_bfloat16* __restrict__ hi,
                          __nv_bfloat16* __restrict__ lo,
                          __half* __restrict__ h16) {
    int row = blockIdx.x;
    int t = threadIdx.x;                 // 0..127
    const float4* xr = (const float4*)(x + (size_t)row * Dc);
    float4 v = xr[t];
    float s  = v.x + v.y + v.z + v.w;
    float s2 = v.x*v.x + v.y*v.y + v.z*v.z + v.w*v.w;
    #pragma unroll
    for (int o = 16; o > 0; o >>= 1) {
        s  += __shfl_xor_sync(0xffffffffu, s,  o);
        s2 += __shfl_xor_sync(0xffffffffu, s2, o);
    }
    __shared__ float sh[8];
    int w = t >> 5;
    if ((t & 31) == 0) { sh[w*2] = s; sh[w*2+1] = s2; }
    __syncthreads();
    s  = sh[0] + sh[2] + sh[4] + sh[6];
    s2 = sh[1] + sh[3] + sh[5] + sh[7];
    float mu  = s * (1.0f / Dc);
    float var = s2 * (1.0f / Dc) - mu * mu;
    float rstd = rsqrtf(var + 1e-5f);
    float4 gv = ((const float4*)g)[t];
    float4 bv = ((const float4*)b)[t];
    float o0 = (v.x - mu) * rstd * gv.x + bv.x;
    float o1 = (v.y - mu) * rstd * gv.y + bv.y;
    float o2 = (v.z - mu) * rstd * gv.z + bv.z;
    float o3 = (v.w - mu) * rstd * gv.w + bv.w;
    size_t base = (size_t)row * Dc + t * 4;
    if (MODE == 0) {
        uint32_t h0, l0, h1, l1;
        split2_bf(o0, o1, h0, l0);
        split2_bf(o2, o3, h1, l1);
        *(uint2*)(hi + base) = make_uint2(h0, h1);
        *(uint2*)(lo + base) = make_uint2(l0, l1);
    } else {
        __half2 p0 = __floats2half2_rn(o0 * 0.03125f, o1 * 0.03125f);
        __half2 p1 = __floats2half2_rn(o2 * 0.03125f, o3 * 0.03125f);
        *(uint2*)(h16 + base) = make_uint2(*reinterpret_cast<uint32_t*>(&p0),
                                           *reinterpret_cast<uint32_t*>(&p1));
    }
}

// ============================================================
// GEMM via mma.sync: C[M,N] = A[M,K] @ B[N,K]^T + bias (+epilogue)
// 128x128 block, 8 warps (2m x 4n, each 64x32), BK=64, 3-stage cp.async
// TERMS=3: bf16, A hi+lo, B hi+lo, 3 mmas (attention path)
// TERMS=2: fp16, A hi only, B hi+lo, 2 mmas (FF path, scale trick)
// EPI: 0=bias->fp32, 1=bias+residual->fp32, 2=bias+GELU->fp16(/32)
// ============================================================
#define TB  16384            // one 128x64 tile of 2B elems

template<int EPI, int TERMS>
__global__ __launch_bounds__(256, 1)
void gemm_mma(const __nv_bfloat16* __restrict__ Ahi, const __nv_bfloat16* __restrict__ Alo,
              const __nv_bfloat16* __restrict__ Bhi, const __nv_bfloat16* __restrict__ Blo,
              const float* __restrict__ bias, const float* __restrict__ res,
              float* __restrict__ C, __half* __restrict__ C16,
              int M, int N, int K)
{
    constexpr int NT  = (TERMS == 3) ? 4 : 3;       // tiles per stage
    constexpr int SSZ = NT * TB;                     // stage bytes
    constexpr int BOFF = (TERMS == 3) ? 2 * TB : TB; // B-hi offset in stage

    extern __shared__ __align__(128) char smem[];
    uint32_t sb = smem_u32(smem);
    int tid = threadIdx.x;
    int lane = tid & 31, wid = tid >> 5;
    int bm = blockIdx.y * 128, bn = blockIdx.x * 128;
    int m0 = (wid & 1) * 64;          // warp tile: 64 (m) x 32 (n)
    int n0 = (wid >> 1) * 32;

    float acc[4][4][4];
    #pragma unroll
    for (int i = 0; i < 4; i++)
        #pragma unroll
        for (int j = 0; j < 4; j++)
            #pragma unroll
            for (int k = 0; k < 4; k++) acc[i][j][k] = 0.0f;

    auto load_stage = [&](int st, int k0) {
        uint32_t base = sb + st * SSZ;
        #pragma unroll
        for (int t = 0; t < 4; t++) {
            int line = tid + t * 256;           // 0..1023
            int r  = line >> 3;                 // row 0..127
            int cc = line & 7;                  // 16B column chunk
            uint32_t d = sw128((uint32_t)(r * 128 + cc * 16));
            size_t aoff = (size_t)(bm + r) * K + k0 + cc * 8;
            size_t boff = (size_t)(bn + r) * K + k0 + cc * 8;
            cp16(base + d, Ahi + aoff);
            if (TERMS == 3) cp16(base + TB + d, Alo + aoff);
            cp16(base + BOFF + d,      Bhi + boff);
            cp16(base + BOFF + TB + d, Blo + boff);
        }
    };

    int nk = K >> 6;
    load_stage(0, 0);  CP_COMMIT();
    load_stage(1, 64); CP_COMMIT();

    int st = 0;                      // stage of current chunk
    for (int ch = 0; ch < nk; ch++) {
        CP_WAIT(1);                  // chunk ch data resident
        __syncthreads();             // visible to all warps; prior compute done
        if (ch + 2 < nk) {
            int st2 = st + 2; if (st2 >= 3) st2 -= 3;
            load_stage(st2, (ch + 2) * 64);
            CP_COMMIT();
        } else {
            CP_COMMIT();             // keep group count in sync for CP_WAIT(1)
        }

        uint32_t abase = sb + st * SSZ;
        uint32_t bbase = abase + BOFF;

        #pragma unroll
        for (int ks = 0; ks < 4; ks++) {
            int k0 = ks * 16;
            uint32_t ahi[4][4], alo[4][4], bhi[4][2], blo[4][2];
            #pragma unroll
            for (int mi = 0; mi < 4; mi++) {
                int row = m0 + mi*16 + (lane & 7) + ((lane >> 3) & 1) * 8;
                int col = k0 + (lane >> 4) * 8;
                uint32_t o = sw128((uint32_t)(row * 128 + col * 2));
                ldm_x4(ahi[mi], abase + o);
                if (TERMS == 3) ldm_x4(alo[mi], abase + TB + o);
            }
            #pragma unroll
            for (int ni = 0; ni < 4; ni++) {
                int row = n0 + ni*8 + (lane & 7);
                int col = k0 + ((lane >> 3) & 1) * 8;
                uint32_t o = sw128((uint32_t)(row * 128 + col * 2));
                ldm_x2(bhi[ni], bbase + o);
                ldm_x2(blo[ni], bbase + TB + o);
            }
            #pragma unroll
            for (int mi = 0; mi < 4; mi++)
                #pragma unroll
                for (int ni = 0; ni < 4; ni++) {
                    if (TERMS == 3) {
                        mma_bf16(acc[mi][ni], ahi[mi], bhi[ni]);
                        mma_bf16(acc[mi][ni], ahi[mi], blo[ni]);
                        mma_bf16(acc[mi][ni], alo[mi], bhi[ni]);
                    } else {
                        mma_f16(acc[mi][ni], ahi[mi], bhi[ni]);
                        mma_f16(acc[mi][ni], ahi[mi], blo[ni]);
                    }
                }
        }
        __syncthreads();             // all warps done with stage st before reuse
        st++; if (st >= 3) st = 0;
    }

    // epilogue: direct stores (each thread owns 2 consecutive cols per frag)
    int gr = lane >> 2, tq = lane & 3;
    #pragma unroll
    for (int mi = 0; mi < 4; mi++) {
        #pragma unroll
        for (int ni = 0; ni < 4; ni++) {
            int col = bn + n0 + ni*8 + tq*2;
            float b0 = bias[col], b1 = bias[col + 1];
            #pragma unroll
            for (int half = 0; half < 2; half++) {
                int row = bm + m0 + mi*16 + gr + half*8;
                float v0 = acc[mi][ni][half*2 + 0] + b0;
                float v1 = acc[mi][ni][half*2 + 1] + b1;
                size_t off = (size_t)row * N + col;
                if (EPI == 1) {
                    float2 r2 = *(const float2*)(res + off);
                    v0 += r2.x; v1 += r2.y;
                    *(float2*)(C + off) = make_float2(v0, v1);
                } else if (EPI == 2) {
                    v0 = 0.5f * v0 * (1.0f + erff(v0 * 0.7071067811865475f));
                    v1 = 0.5f * v1 * (1.0f + erff(v1 * 0.7071067811865475f));
                    __half2 p = __floats2half2_rn(v0 * 0.03125f, v1 * 0.03125f);
                    *(uint32_t*)(C16 + off) = *reinterpret_cast<uint32_t*>(&p);
                } else {
                    *(float2*)(C + off) = make_float2(v0, v1);
                }
            }
        }
    }
}

// ============================================================
// Local attention: one warp per (b,s,h); outputs ctx as bf16 hi/lo
// ============================================================
__global__ void attn_kernel(const float* __restrict__ qkv,
                            __nv_bfloat16* __restrict__ ctxhi,
                            __nv_bfloat16* __restrict__ ctxlo) {
    int gwarp = (blockIdx.x * blockDim.x + threadIdx.x) >> 5;
    int lane = threadIdx.x & 31;
    int h  = gwarp & (Hc - 1);
    int bs = gwarp >> 3;
    int s  = bs & (Sc - 1);
    int rowbase = bs - s;

    const float* qr = qkv + (size_t)bs * D3 + h * Dhc;
    float q0 = qr[lane], q1 = qr[lane + 32];

    float e[9];
    float mx = -INFINITY;
    #pragma unroll
    for (int jj = 0; jj < 9; jj++) {
        int j = s - 4 + jj;
        float sc = -INFINITY;
        if (j >= 0 && j < Sc) {
            const float* kr = qkv + (size_t)(rowbase + j) * D3 + Dc + h * Dhc;
            float p = q0 * kr[lane] + q1 * kr[lane + 32];
            #pragma unroll
            for (int o = 16; o > 0; o >>= 1)
                p += __shfl_xor_sync(0xffffffffu, p, o);
            sc = p * 0.125f;
        }
        e[jj] = sc;
        mx = fmaxf(mx, sc);
    }
    float sum = 0.0f;
    #pragma unroll
    for (int jj = 0; jj < 9; jj++) {
        e[jj] = expf(e[jj] - mx);
        sum += e[jj];
    }
    float inv = 1.0f / sum;
    float c0 = 0.0f, c1 = 0.0f;
    #pragma unroll
    for (int jj = 0; jj < 9; jj++) {
        int j = s - 4 + jj;
        if (j >= 0 && j < Sc) {
            const float* vr = qkv + (size_t)(rowbase + j) * D3 + 2*Dc + h * Dhc;
            float w = e[jj] * inv;
            c0 = fmaf(w, vr[lane],      c0);
            c1 = fmaf(w, vr[lane + 32], c1);
        }
    }
    size_t i0 = (size_t)bs * Dc + h * Dhc + lane;
    size_t i1 = i0 + 32;
    __nv_bfloat16 h0 = __float2bfloat16(c0);
    __nv_bfloat16 h1 = __float2bfloat16(c1);
    ctxhi[i0] = h0;
    ctxhi[i1] = h1;
    ctxlo[i0] = __float2bfloat16(c0 - __bfloat162float(h0));
    ctxlo[i1] = __float2bfloat16(c1 - __bfloat162float(h1));
}

// ============================================================
extern "C" void kernel_launch(void* const* d_in, const int* in_sizes, int n_in,
                              void* d_out, int out_size) {
    const float* x     = (const float*)d_in[0];
    const float* in_w  = (const float*)d_in[1];
    const float* in_b  = (const float*)d_in[2];
    const float* out_w = (const float*)d_in[3];
    const float* out_b = (const float*)d_in[4];
    const float* ff_w1 = (const float*)d_in[5];
    const float* ff_b1 = (const float*)d_in[6];
    const float* ff_w2 = (const float*)d_in[7];
    const float* ff_b2 = (const float*)d_in[8];
    const float* ln1_g = (const float*)d_in[9];
    const float* ln1_b = (const float*)d_in[10];
    const float* ln2_g = (const float*)d_in[11];
    const float* ln2_b = (const float*)d_in[12];
    float* out = (float*)d_out;

    __nv_bfloat16 *whi, *wlo, *acthi, *actlo;
    __half *fwhi, *fwlo, *a16, *ff16;
    float *qkv, *x1;
    cudaGetSymbolAddress((void**)&whi,   g_whi);
    cudaGetSymbolAddress((void**)&wlo,   g_wlo);
    cudaGetSymbolAddress((void**)&fwhi,  g_fwhi);
    cudaGetSymbolAddress((void**)&fwlo,  g_fwlo);
    cudaGetSymbolAddress((void**)&acthi, g_acthi);
    cudaGetSymbolAddress((void**)&actlo, g_actlo);
    cudaGetSymbolAddress((void**)&a16,   g_a16);
    cudaGetSymbolAddress((void**)&ff16,  g_ff16);
    cudaGetSymbolAddress((void**)&qkv,   g_qkv);
    cudaGetSymbolAddress((void**)&x1,    g_x1);

    const int SM3 = 3 * 4 * TB;   // 196608
    const int SM2 = 3 * 3 * TB;   // 147456
    cudaFuncSetAttribute(gemm_mma<0,3>, cudaFuncAttributeMaxDynamicSharedMemorySize, SM3);
    cudaFuncSetAttribute(gemm_mma<1,3>, cudaFuncAttributeMaxDynamicSharedMemorySize, SM3);
    cudaFuncSetAttribute(gemm_mma<2,2>, cudaFuncAttributeMaxDynamicSharedMemorySize, SM2);
    cudaFuncSetAttribute(gemm_mma<1,2>, cudaFuncAttributeMaxDynamicSharedMemorySize, SM2);

    // weight conversions
    wconv_bf16<<<768,  256>>>(in_w,  whi,            wlo,            196608);
    wconv_bf16<<<256,  256>>>(out_w, whi + WOFF_OUT, wlo + WOFF_OUT, 65536);
    wconv_f16s<<<1024, 256>>>(ff_w1, fwhi,             fwlo,             262144);
    wconv_f16s<<<1024, 256>>>(ff_w2, fwhi + FWOFF_FF2, fwlo + FWOFF_FF2, 262144);

    // 1) act = split_bf16(LN1(x))
    ln_kernel<0><<<Mrows, 128>>>(x, ln1_g, ln1_b, acthi, actlo, nullptr);
    // 2) qkv = act @ in_w^T + in_b   (3-term bf16, fp32 out)
    gemm_mma<0,3><<<dim3(D3/128, Mrows/128), 256, SM3>>>(
        acthi, actlo, whi, wlo, in_b, nullptr, qkv, nullptr, Mrows, D3, Dc);
    // 3) ctx = attention(qkv) -> bf16 hi/lo
    attn_kernel<<<(Mrows * Hc * 32) / 256, 256>>>(qkv, acthi, actlo);
    // 4) x1 = x + ctx @ out_w^T + out_b  (3-term bf16)
    gemm_mma<1,3><<<dim3(Dc/128, Mrows/128), 256, SM3>>>(
        acthi, actlo, whi + WOFF_OUT, wlo + WOFF_OUT, out_b, x, x1, nullptr,
        Mrows, Dc, Dc);
    // 5) a16 = fp16(LN2(x1)/32)
    ln_kernel<1><<<Mrows, 128>>>(x1, ln2_g, ln2_b, nullptr, nullptr, a16);
    // 6) ff16 = fp16(gelu(a16 @ (32*ff_w1)^T + ff_b1)/32)   (2-term fp16)
    gemm_mma<2,2><<<dim3(DffC/128, Mrows/128), 256, SM2>>>(
        (const __nv_bfloat16*)a16, nullptr,
        (const __nv_bfloat16*)fwhi, (const __nv_bfloat16*)fwlo,
        ff_b1, nullptr, nullptr, ff16, Mrows, DffC, Dc);
    // 7) out = x1 + ff16 @ (32*ff_w2)^T + ff_b2   (2-term fp16)
    gemm_mma<1,2><<<dim3(Dc/128, Mrows/128), 256, SM2>>>(
        (const __nv_bfloat16*)ff16, nullptr,
        (const __nv_bfloat16*)(fwhi + FWOFF_FF2), (const __nv_bfloat16*)(fwlo + FWOFF_FF2),
        ff_b2, x1, out, nullptr, Mrows, Dc, DffC);
}

// round 5
// speedup vs baseline: 3.6401x; 1.0881x over previous
#include <cuda_runtime.h>
#include <cuda_fp16.h>
#include <math.h>
#include <stdint.h>

// Problem constants
#define Bc   4
#define Sc   2048
#define Dc   512
#define Hc   8
#define Dhc  64
#define Mrows (Bc*Sc)      // 8192
#define D3   (3*Dc)        // 1536
#define DffC (4*Dc)        // 2048

// ---- scratch (device globals; no cudaMalloc allowed) ----
// weights as fp16(32*w), hi + lo residual
__device__ __half g_fwhi[3145728];
__device__ __half g_fwlo[3145728];
#define FW_IN   0
#define FW_OUT  786432
#define FW_FF1  1048576
#define FW_FF2  2097152
// activations as fp16(act/32)
__device__ __half g_a16 [(size_t)Mrows * Dc];
__device__ __half g_ff16[(size_t)Mrows * DffC];
__device__ float  g_qkv [(size_t)Mrows * D3];
__device__ float  g_x1  [(size_t)Mrows * Dc];

// ============================================================
// helpers
// ============================================================
__device__ __forceinline__ uint32_t smem_u32(const void* p) {
    uint32_t a;
    asm("{ .reg .u64 t; cvta.to.shared.u64 t, %1; cvt.u32.u64 %0, t; }" : "=r"(a) : "l"(p));
    return a;
}
__device__ __forceinline__ uint32_t sw128(uint32_t o) { return o ^ ((o >> 3) & 0x70); }

__device__ __forceinline__ void split2_f16(float x, float y, uint32_t& hi, uint32_t& lo) {
    __half2 h = __floats2half2_rn(x, y);
    float rx = x - __half2float(h.x);
    float ry = y - __half2float(h.y);
    __half2 l = __floats2half2_rn(rx, ry);
    hi = *reinterpret_cast<uint32_t*>(&h);
    lo = *reinterpret_cast<uint32_t*>(&l);
}

__device__ __forceinline__ void cp16(uint32_t dst, const void* src) {
    asm volatile("cp.async.cg.shared.global [%0], [%1], 16;" :: "r"(dst), "l"(src) : "memory");
}
#define CP_COMMIT() asm volatile("cp.async.commit_group;" ::: "memory")
#define CP_WAIT(n)  asm volatile("cp.async.wait_group %0;" :: "n"(n) : "memory")

__device__ __forceinline__ void ldm_x4(uint32_t* r, uint32_t addr) {
    asm volatile("ldmatrix.sync.aligned.m8n8.x4.shared.b16 {%0,%1,%2,%3}, [%4];"
                 : "=r"(r[0]), "=r"(r[1]), "=r"(r[2]), "=r"(r[3]) : "r"(addr));
}
__device__ __forceinline__ void ldm_x2(uint32_t* r, uint32_t addr) {
    asm volatile("ldmatrix.sync.aligned.m8n8.x2.shared.b16 {%0,%1}, [%2];"
                 : "=r"(r[0]), "=r"(r[1]) : "r"(addr));
}
__device__ __forceinline__ void mma_f16(float* c, const uint32_t* a, const uint32_t* b) {
    asm volatile("mma.sync.aligned.m16n8k16.row.col.f32.f16.f16.f32 "
                 "{%0,%1,%2,%3}, {%4,%5,%6,%7}, {%8,%9}, {%0,%1,%2,%3};"
                 : "+f"(c[0]), "+f"(c[1]), "+f"(c[2]), "+f"(c[3])
                 : "r"(a[0]), "r"(a[1]), "r"(a[2]), "r"(a[3]), "r"(b[0]), "r"(b[1]));
}

// ============================================================
// weight conversion: w -> fp16(32*w) hi + lo  (once per launch)
// ============================================================
__global__ void wconv_f16s(const float* __restrict__ w,
                           __half* __restrict__ hi,
                           __half* __restrict__ lo, int n4) {
    int i = blockIdx.x * 256 + threadIdx.x;
    if (i >= n4) return;
    float4 v = ((const float4*)w)[i];
    uint32_t h0, l0, h1, l1;
    split2_f16(v.x * 32.0f, v.y * 32.0f, h0, l0);
    split2_f16(v.z * 32.0f, v.w * 32.0f, h1, l1);
    ((uint2*)hi)[i] = make_uint2(h0, h1);
    ((uint2*)lo)[i] = make_uint2(l0, l1);
}

// ============================================================
// LayerNorm -> fp16(out/32)
// ============================================================
__global__ void ln_kernel(const float* __restrict__ x,
                          const float* __restrict__ g,
                          const float* __restrict__ b,
                          __half* __restrict__ h16) {
    int row = blockIdx.x;
    int t = threadIdx.x;                 // 0..127
    const float4* xr = (const float4*)(x + (size_t)row * Dc);
    float4 v = xr[t];
    float s  = v.x + v.y + v.z + v.w;
    float s2 = v.x*v.x + v.y*v.y + v.z*v.z + v.w*v.w;
    #pragma unroll
    for (int o = 16; o > 0; o >>= 1) {
        s  += __shfl_xor_sync(0xffffffffu, s,  o);
        s2 += __shfl_xor_sync(0xffffffffu, s2, o);
    }
    __shared__ float sh[8];
    int w = t >> 5;
    if ((t & 31) == 0) { sh[w*2] = s; sh[w*2+1] = s2; }
    __syncthreads();
    s  = sh[0] + sh[2] + sh[4] + sh[6];
    s2 = sh[1] + sh[3] + sh[5] + sh[7];
    float mu  = s * (1.0f / Dc);
    float var = s2 * (1.0f / Dc) - mu * mu;
    float rstd = rsqrtf(var + 1e-5f);
    float4 gv = ((const float4*)g)[t];
    float4 bv = ((const float4*)b)[t];
    float o0 = (v.x - mu) * rstd * gv.x + bv.x;
    float o1 = (v.y - mu) * rstd * gv.y + bv.y;
    float o2 = (v.z - mu) * rstd * gv.z + bv.z;
    float o3 = (v.w - mu) * rstd * gv.w + bv.w;
    __half2 p0 = __floats2half2_rn(o0 * 0.03125f, o1 * 0.03125f);
    __half2 p1 = __floats2half2_rn(o2 * 0.03125f, o3 * 0.03125f);
    size_t base = (size_t)row * Dc + t * 4;
    *(uint2*)(h16 + base) = make_uint2(*reinterpret_cast<uint32_t*>(&p0),
                                       *reinterpret_cast<uint32_t*>(&p1));
}

// ============================================================
// 2-term fp16 GEMM via mma.sync:
//   C[M,N] = (A/32)[M,K] @ (32*B)[N,K]^T + bias  (fp32 accum, exact scale cancel)
//   terms: Ahi*Bhi + Ahi*Blo
// 128x128 block, 8 warps (2m x 4n, each 64x32), BK=64, 2-stage cp.async,
// 96KB smem -> 2 CTAs/SM.
// EPI: 0=bias->fp32, 1=bias+residual->fp32, 2=bias+GELU->fp16(/32)
// ============================================================
#define TB  16384            // one 128x64 fp16 tile
#define SSZ (3*TB)           // stage: Ahi, Bhi, Blo
#define SM_SZ (2*SSZ)        // 98304

template<int EPI>
__global__ __launch_bounds__(256, 2)
void gemm_mma(const __half* __restrict__ Ahi,
              const __half* __restrict__ Bhi, const __half* __restrict__ Blo,
              const float* __restrict__ bias, const float* __restrict__ res,
              float* __restrict__ C, __half* __restrict__ C16,
              int M, int N, int K)
{
    extern __shared__ __align__(128) char smem[];
    uint32_t sb = smem_u32(smem);
    int tid = threadIdx.x;
    int lane = tid & 31, wid = tid >> 5;
    int bm = blockIdx.y * 128, bn = blockIdx.x * 128;
    int m0 = (wid & 1) * 64;          // warp tile: 64 (m) x 32 (n)
    int n0 = (wid >> 1) * 32;

    float acc[4][4][4];
    #pragma unroll
    for (int i = 0; i < 4; i++)
        #pragma unroll
        for (int j = 0; j < 4; j++)
            #pragma unroll
            for (int k = 0; k < 4; k++) acc[i][j][k] = 0.0f;

    auto load_stage = [&](int st, int k0) {
        uint32_t base = sb + st * SSZ;
        #pragma unroll
        for (int t = 0; t < 4; t++) {
            int line = tid + t * 256;           // 0..1023
            int r  = line >> 3;                 // row 0..127
            int cc = line & 7;                  // 16B column chunk
            uint32_t d = sw128((uint32_t)(r * 128 + cc * 16));
            size_t aoff = (size_t)(bm + r) * K + k0 + cc * 8;
            size_t boff = (size_t)(bn + r) * K + k0 + cc * 8;
            cp16(base + d,          Ahi + aoff);
            cp16(base + TB + d,     Bhi + boff);
            cp16(base + 2*TB + d,   Blo + boff);
        }
    };

    int nk = K >> 6;
    load_stage(0, 0);
    CP_COMMIT();

    for (int ch = 0; ch < nk; ch++) {
        if (ch + 1 < nk) {
            load_stage((ch + 1) & 1, (ch + 1) * 64);
            CP_COMMIT();
            CP_WAIT(1);
        } else {
            CP_WAIT(0);
        }
        __syncthreads();

        uint32_t abase = sb + (ch & 1) * SSZ;
        uint32_t bbase = abase + TB;

        #pragma unroll
        for (int ks = 0; ks < 4; ks++) {
            int k0 = ks * 16;
            uint32_t ahi[4][4], bhi[4][2], blo[4][2];
            #pragma unroll
            for (int mi = 0; mi < 4; mi++) {
                int row = m0 + mi*16 + (lane & 7) + ((lane >> 3) & 1) * 8;
                int col = k0 + (lane >> 4) * 8;
                uint32_t o = sw128((uint32_t)(row * 128 + col * 2));
                ldm_x4(ahi[mi], abase + o);
            }
            #pragma unroll
            for (int ni = 0; ni < 4; ni++) {
                int row = n0 + ni*8 + (lane & 7);
                int col = k0 + ((lane >> 3) & 1) * 8;
                uint32_t o = sw128((uint32_t)(row * 128 + col * 2));
                ldm_x2(bhi[ni], bbase + o);
                ldm_x2(blo[ni], bbase + TB + o);
            }
            #pragma unroll
            for (int mi = 0; mi < 4; mi++)
                #pragma unroll
                for (int ni = 0; ni < 4; ni++) {
                    mma_f16(acc[mi][ni], ahi[mi], bhi[ni]);
                    mma_f16(acc[mi][ni], ahi[mi], blo[ni]);
                }
        }
        __syncthreads();
    }

    // epilogue: direct stores (each thread owns 2 consecutive cols per frag)
    int gr = lane >> 2, tq = lane & 3;
    #pragma unroll
    for (int mi = 0; mi < 4; mi++) {
        #pragma unroll
        for (int ni = 0; ni < 4; ni++) {
            int col = bn + n0 + ni*8 + tq*2;
            float b0 = bias[col], b1 = bias[col + 1];
            #pragma unroll
            for (int half = 0; half < 2; half++) {
                int row = bm + m0 + mi*16 + gr + half*8;
                float v0 = acc[mi][ni][half*2 + 0] + b0;
                float v1 = acc[mi][ni][half*2 + 1] + b1;
                size_t off = (size_t)row * N + col;
                if (EPI == 1) {
                    float2 r2 = *(const float2*)(res + off);
                    v0 += r2.x; v1 += r2.y;
                    *(float2*)(C + off) = make_float2(v0, v1);
                } else if (EPI == 2) {
                    v0 = 0.5f * v0 * (1.0f + erff(v0 * 0.7071067811865475f));
                    v1 = 0.5f * v1 * (1.0f + erff(v1 * 0.7071067811865475f));
                    __half2 p = __floats2half2_rn(v0 * 0.03125f, v1 * 0.03125f);
                    *(uint32_t*)(C16 + off) = *reinterpret_cast<uint32_t*>(&p);
                } else {
                    *(float2*)(C + off) = make_float2(v0, v1);
                }
            }
        }
    }
}

// ============================================================
// Local attention: one warp per (b,s,h); fp32 qkv in, fp16(ctx/32) out
// ============================================================
__global__ void attn_kernel(const float* __restrict__ qkv,
                            __half* __restrict__ ctx16) {
    int gwarp = (blockIdx.x * blockDim.x + threadIdx.x) >> 5;
    int lane = threadIdx.x & 31;
    int h  = gwarp & (Hc - 1);
    int bs = gwarp >> 3;
    int s  = bs & (Sc - 1);
    int rowbase = bs - s;

    const float* qr = qkv + (size_t)bs * D3 + h * Dhc;
    float q0 = qr[lane], q1 = qr[lane + 32];

    float e[9];
    float mx = -INFINITY;
    #pragma unroll
    for (int jj = 0; jj < 9; jj++) {
        int j = s - 4 + jj;
        float sc = -INFINITY;
        if (j >= 0 && j < Sc) {
            const float* kr = qkv + (size_t)(rowbase + j) * D3 + Dc + h * Dhc;
            float p = q0 * kr[lane] + q1 * kr[lane + 32];
            #pragma unroll
            for (int o = 16; o > 0; o >>= 1)
                p += __shfl_xor_sync(0xffffffffu, p, o);
            sc = p * 0.125f;
        }
        e[jj] = sc;
        mx = fmaxf(mx, sc);
    }
    float sum = 0.0f;
    #pragma unroll
    for (int jj = 0; jj < 9; jj++) {
        e[jj] = expf(e[jj] - mx);
        sum += e[jj];
    }
    float inv = 1.0f / sum;
    float c0 = 0.0f, c1 = 0.0f;
    #pragma unroll
    for (int jj = 0; jj < 9; jj++) {
        int j = s - 4 + jj;
        if (j >= 0 && j < Sc) {
            const float* vr = qkv + (size_t)(rowbase + j) * D3 + 2*Dc + h * Dhc;
            float w = e[jj] * inv;
            c0 = fmaf(w, vr[lane],      c0);
            c1 = fmaf(w, vr[lane + 32], c1);
        }
    }
    size_t i0 = (size_t)bs * Dc + h * Dhc + lane;
    ctx16[i0]      = __float2half(c0 * 0.03125f);
    ctx16[i0 + 32] = __float2half(c1 * 0.03125f);
}

// ============================================================
extern "C" void kernel_launch(void* const* d_in, const int* in_sizes, int n_in,
                              void* d_out, int out_size) {
    const float* x     = (const float*)d_in[0];
    const float* in_w  = (const float*)d_in[1];
    const float* in_b  = (const float*)d_in[2];
    const float* out_w = (const float*)d_in[3];
    const float* out_b = (const float*)d_in[4];
    const float* ff_w1 = (const float*)d_in[5];
    const float* ff_b1 = (const float*)d_in[6];
    const float* ff_w2 = (const float*)d_in[7];
    const float* ff_b2 = (const float*)d_in[8];
    const float* ln1_g = (const float*)d_in[9];
    const float* ln1_b = (const float*)d_in[10];
    const float* ln2_g = (const float*)d_in[11];
    const float* ln2_b = (const float*)d_in[12];
    float* out = (float*)d_out;

    __half *fwhi, *fwlo, *a16, *ff16;
    float *qkv, *x1;
    cudaGetSymbolAddress((void**)&fwhi, g_fwhi);
    cudaGetSymbolAddress((void**)&fwlo, g_fwlo);
    cudaGetSymbolAddress((void**)&a16,  g_a16);
    cudaGetSymbolAddress((void**)&ff16, g_ff16);
    cudaGetSymbolAddress((void**)&qkv,  g_qkv);
    cudaGetSymbolAddress((void**)&x1,   g_x1);

    cudaFuncSetAttribute(gemm_mma<0>, cudaFuncAttributeMaxDynamicSharedMemorySize, SM_SZ);
    cudaFuncSetAttribute(gemm_mma<1>, cudaFuncAttributeMaxDynamicSharedMemorySize, SM_SZ);
    cudaFuncSetAttribute(gemm_mma<2>, cudaFuncAttributeMaxDynamicSharedMemorySize, SM_SZ);

    // weight conversions (fp16(32*w) hi/lo)
    wconv_f16s<<<768,  256>>>(in_w,  fwhi + FW_IN,  fwlo + FW_IN,  196608);
    wconv_f16s<<<256,  256>>>(out_w, fwhi + FW_OUT, fwlo + FW_OUT, 65536);
    wconv_f16s<<<1024, 256>>>(ff_w1, fwhi + FW_FF1, fwlo + FW_FF1, 262144);
    wconv_f16s<<<1024, 256>>>(ff_w2, fwhi + FW_FF2, fwlo + FW_FF2, 262144);

    // 1) a16 = fp16(LN1(x)/32)
    ln_kernel<<<Mrows, 128>>>(x, ln1_g, ln1_b, a16);
    // 2) qkv = a16 @ (32*in_w)^T + in_b   (fp32 out)
    gemm_mma<0><<<dim3(D3/128, Mrows/128), 256, SM_SZ>>>(
        a16, fwhi + FW_IN, fwlo + FW_IN, in_b, nullptr, qkv, nullptr,
        Mrows, D3, Dc);
    // 3) a16 = fp16(attention(qkv)/32)
    attn_kernel<<<(Mrows * Hc * 32) / 256, 256>>>(qkv, a16);
    // 4) x1 = x + a16 @ (32*out_w)^T + out_b
    gemm_mma<1><<<dim3(Dc/128, Mrows/128), 256, SM_SZ>>>(
        a16, fwhi + FW_OUT, fwlo + FW_OUT, out_b, x, x1, nullptr,
        Mrows, Dc, Dc);
    // 5) a16 = fp16(LN2(x1)/32)
    ln_kernel<<<Mrows, 128>>>(x1, ln2_g, ln2_b, a16);
    // 6) ff16 = fp16(gelu(a16 @ (32*ff_w1)^T + ff_b1)/32)
    gemm_mma<2><<<dim3(DffC/128, Mrows/128), 256, SM_SZ>>>(
        a16, fwhi + FW_FF1, fwlo + FW_FF1, ff_b1, nullptr, nullptr, ff16,
        Mrows, DffC, Dc);
    // 7) out = x1 + ff16 @ (32*ff_w2)^T + ff_b2
    gemm_mma<1><<<dim3(Dc/128, Mrows/128), 256, SM_SZ>>>(
        ff16, fwhi + FW_FF2, fwlo + FW_FF2, ff_b2, x1, out, nullptr,
        Mrows, Dc, DffC);
}